// round 17
// baseline (speedup 1.0000x reference)
#include <cuda_runtime.h>
#include <cuda_fp16.h>
#include <math.h>
#include <stdint.h>

#define NROWS 32768      // B*S
#define FFN   2048
#define EMB   512
#define NCHUNK 4
#define HBLKS_PER_CHUNK 128      // 512 h-blocks total / 4
#define MTILES_PER_CHUNK 64      // 256 m-tiles total / 4

// ---------------- scratch ---------------------------------------------------
__device__ __half g_H[(size_t)NROWS * FFN];        // 128 MB (fp16 of H)
__device__ __half g_Wh[EMB * FFN];                 // 2 MB  (fp16 of W2)

// ---------------------------------------------------------------------------
// Kernel 1 (fused, chunked): EV (closed-form circuit) + H = relu(EV@W1^T+b1)
// -> fp16.  Chunk 0 additionally converts ALL of W2 -> fp16 (gemm chunk 0
// needs the full B matrix).  One block owns 64 rows x all 2048 columns.
// ---------------------------------------------------------------------------
#define HROWS 64
__global__ void __launch_bounds__(256)
h_fused_kernel(const float* __restrict__ x, const float* __restrict__ params,
               const float* __restrict__ W1, const float* __restrict__ b1,
               const float* __restrict__ W2, int blk_base, int do_w2) {
    __shared__ float sA[8], sC[8];
    __shared__ float sEV[HROWS][8];
    const int tid = threadIdx.x;
    const int r0  = (blk_base + blockIdx.x) * HROWS;

    if (do_w2) {   // whole W2: 524288 float2 over 32768 threads = 16 each
        int g = blockIdx.x * 256 + tid;
#pragma unroll
        for (int i = 0; i < 16; i++) {
            int idx = g + (i << 15);             // stride 32768
            float2 v = ((const float2*)W2)[idx];
            ((__half2*)g_Wh)[idx] = __floats2half2_rn(v.x, v.y);
        }
    }

    if (tid < 8) {
        float a = params[tid * 3 + 0];
        float b = params[tid * 3 + 1];
        float c = params[tid * 3 + 2];
        float sa, ca, sb, cb, sc, cc;
        sincosf(a, &sa, &ca);
        sincosf(b, &sb, &cb);
        sincosf(c, &sc, &cc);
        sA[tid] = ca * cc + sa * sb * sc;
        sC[tid] = cb * sc;
    }
    __syncthreads();

    if (tid < HROWS) {
        int row = r0 + tid;
        float z[8];
#pragma unroll
        for (int i = 0; i < 8; i++) {
            float sx, cx;
            sincosf(x[row * 8 + i], &sx, &cx);
            z[i] = sA[i] * cx - sC[i] * sx;
        }
        float ev[8];
        float pre = z[0];
#pragma unroll
        for (int k = 1; k < 8; k++) { pre *= z[k]; ev[k] = pre; }
        float suf = 1.0f;
#pragma unroll
        for (int k = 7; k >= 1; k--) suf *= z[k];
        ev[0] = suf;
#pragma unroll
        for (int k = 0; k < 8; k++) sEV[tid][k] = ev[k];
    }

    const int c0 = tid * 8;
    float4 w0[8], w1[8];
    float bb[8];
#pragma unroll
    for (int j = 0; j < 8; j++) {
        w0[j] = *(const float4*)&W1[(c0 + j) * 8];
        w1[j] = *(const float4*)&W1[(c0 + j) * 8 + 4];
        bb[j] = b1[c0 + j];
    }
    __syncthreads();

#pragma unroll 2
    for (int r = 0; r < HROWS; r++) {
        float4 e0 = *(const float4*)&sEV[r][0];
        float4 e1 = *(const float4*)&sEV[r][4];
        float h[8];
#pragma unroll
        for (int j = 0; j < 8; j++) {
            h[j] = bb[j]
                 + e0.x * w0[j].x + e0.y * w0[j].y + e0.z * w0[j].z + e0.w * w0[j].w
                 + e1.x * w1[j].x + e1.y * w1[j].y + e1.z * w1[j].z + e1.w * w1[j].w;
        }
        __half2 p0 = __floats2half2_rn(fmaxf(h[0], 0.0f), fmaxf(h[1], 0.0f));
        __half2 p1 = __floats2half2_rn(fmaxf(h[2], 0.0f), fmaxf(h[3], 0.0f));
        __half2 p2 = __floats2half2_rn(fmaxf(h[4], 0.0f), fmaxf(h[5], 0.0f));
        __half2 p3 = __floats2half2_rn(fmaxf(h[6], 0.0f), fmaxf(h[7], 0.0f));
        uint4 st;
        st.x = reinterpret_cast<unsigned&>(p0);
        st.y = reinterpret_cast<unsigned&>(p1);
        st.z = reinterpret_cast<unsigned&>(p2);
        st.w = reinterpret_cast<unsigned&>(p3);
        *(uint4*)&g_H[(size_t)(r0 + r) * FFN + c0] = st;
    }
}

// ---------------------------------------------------------------------------
// Kernel 2: OUT = H @ W2^T + b2, mma.sync fp16 single pass, fp32 acc.
// CTA 128x128, BK=64, 4 warps (2x2, warp tile 64x64), 3-stage cp.async,
// 96KB dynamic smem, 2 CTAs/SM.  (R14-proven; bm chunk offset added.)
// ---------------------------------------------------------------------------
#define BM 128
#define BN 128
#define BK 64
#define NT (FFN / BK)             // 32
#define STG 32768                 // A 0 (16384), B 16384 (16384)
#define SMEM_TOTAL (3 * STG)      // 98304

#define CP16(dst, src) \
    asm volatile("cp.async.cg.shared.global [%0], [%1], 16;\n" :: "r"(dst), "l"(src))

__device__ __forceinline__ void ldsm4(unsigned* r, unsigned a) {
    asm volatile("ldmatrix.sync.aligned.m8n8.x4.shared.b16 {%0,%1,%2,%3}, [%4];"
                 : "=r"(r[0]), "=r"(r[1]), "=r"(r[2]), "=r"(r[3]) : "r"(a));
}

__device__ __forceinline__ void mma16816(float* c, const unsigned* a, const unsigned* b) {
    asm volatile("mma.sync.aligned.m16n8k16.row.col.f32.f16.f16.f32 "
                 "{%0,%1,%2,%3}, {%4,%5,%6,%7}, {%8,%9}, {%0,%1,%2,%3};"
                 : "+f"(c[0]), "+f"(c[1]), "+f"(c[2]), "+f"(c[3])
                 : "r"(a[0]), "r"(a[1]), "r"(a[2]), "r"(a[3]), "r"(b[0]), "r"(b[1]));
}

// 128B rows, 8 chunks of 16B, full SW128 swizzle
__device__ __forceinline__ unsigned swz(int row, int ch) {
    return (unsigned)(row * 128 + ((ch ^ (row & 7)) << 4));
}

__device__ __forceinline__ void load_stage(unsigned st, int bm, int bn, int tid, int k0) {
#pragma unroll
    for (int i = 0; i < 8; i++) {               // A: 1024 chunks of 16B
        int id = tid + (i << 7);
        int r = id >> 3, c = id & 7;
        size_t g = (size_t)(bm + r) * FFN + k0 + c * 8;
        CP16(st + swz(r, c), g_H + g);
    }
#pragma unroll
    for (int i = 0; i < 8; i++) {               // B: 1024 chunks of 16B
        int id = tid + (i << 7);
        int r = id >> 3, c = id & 7;
        size_t g = (size_t)(bn + r) * FFN + k0 + c * 8;
        CP16(st + 16384 + swz(r, c), g_Wh + g);
    }
}

__global__ void __launch_bounds__(128, 2)
mma_gemm(const float* __restrict__ bias, float* __restrict__ C, int mbase) {
    extern __shared__ __align__(128) unsigned char smem[];
    const int tid  = threadIdx.x;
    const int warp = tid >> 5, lane = tid & 31;
    const int wm = warp & 1;                 // 2 m-groups of 64 rows
    const int wn = warp >> 1;                // 2 n-groups of 64 cols
    const int bm = (mbase + blockIdx.y) * BM, bn = blockIdx.x * BN;
    const unsigned sbase = (unsigned)__cvta_generic_to_shared(smem);

    float acc[4][8][4];                      // [mf][nf][frag]
#pragma unroll
    for (int i = 0; i < 4; i++)
#pragma unroll
        for (int j = 0; j < 8; j++)
#pragma unroll
            for (int k = 0; k < 4; k++) acc[i][j][k] = 0.0f;

    load_stage(sbase,       bm, bn, tid, 0);
    asm volatile("cp.async.commit_group;\n");
    load_stage(sbase + STG, bm, bn, tid, BK);
    asm volatile("cp.async.commit_group;\n");

    for (int t = 0; t < NT; t++) {
        if (t + 1 < NT) asm volatile("cp.async.wait_group 1;\n" ::: "memory");
        else            asm volatile("cp.async.wait_group 0;\n" ::: "memory");
        __syncthreads();          // single barrier per stage (3-stage ring)

        if (t + 2 < NT) {
            load_stage(sbase + ((t + 2) % 3) * STG, bm, bn, tid, (t + 2) * BK);
            asm volatile("cp.async.commit_group;\n");
        }

        unsigned st = sbase + (t % 3) * STG;
#pragma unroll
        for (int kk = 0; kk < 4; kk++) {     // four k16 chunks of BK=64
            unsigned ah[4][4], bh[4][4];
#pragma unroll
            for (int mf = 0; mf < 4; mf++) {     // A frags: m64 x k16
                int r  = wm * 64 + mf * 16 + (lane & 15);
                int ch = kk * 2 + (lane >> 4);
                ldsm4(ah[mf], st + swz(r, ch));
            }
#pragma unroll
            for (int nb = 0; nb < 4; nb++) {     // B frags: n64
                int n  = wn * 64 + nb * 16 + (lane & 7) + ((lane >> 4) & 1) * 8;
                int ch = kk * 2 + ((lane >> 3) & 1);
                ldsm4(bh[nb], st + 16384 + swz(n, ch));
            }
#pragma unroll
            for (int mf = 0; mf < 4; mf++)
#pragma unroll
                for (int nf = 0; nf < 8; nf++)
                    mma16816(acc[mf][nf], ah[mf], &bh[nf >> 1][(nf & 1) * 2]);
        }
    }

    // epilogue: add bias
#pragma unroll
    for (int mf = 0; mf < 4; mf++) {
        int r0 = bm + wm * 64 + mf * 16 + (lane >> 2);
#pragma unroll
        for (int nf = 0; nf < 8; nf++) {
            int cc = bn + wn * 64 + nf * 8 + (lane & 3) * 2;
            float2 b2 = *(const float2*)&bias[cc];
            float2 v0 = make_float2(acc[mf][nf][0] + b2.x, acc[mf][nf][1] + b2.y);
            float2 v1 = make_float2(acc[mf][nf][2] + b2.x, acc[mf][nf][3] + b2.y);
            *(float2*)&C[(size_t)r0 * EMB + cc]       = v0;
            *(float2*)&C[(size_t)(r0 + 8) * EMB + cc] = v1;
        }
    }
}

// ---------------------------------------------------------------------------
// Launch: chunked fork-join overlap of h_fused (producer) and mma_gemm
// (consumer) across row chunks.  Standard capturable multi-stream pattern:
// side streams join the capture via events and merge back at the end.
// Streams/events are host objects (no device memory).
// ---------------------------------------------------------------------------
extern "C" void kernel_launch(void* const* d_in, const int* in_sizes, int n_in,
                              void* d_out, int out_size) {
    const float* x      = (const float*)d_in[0];  // [16,2048,8]
    const float* params = (const float*)d_in[1];  // [8,3]
    const float* W1     = (const float*)d_in[2];  // [2048,8]
    const float* b1     = (const float*)d_in[3];  // [2048]
    const float* W2     = (const float*)d_in[4];  // [512,2048]
    const float* b2     = (const float*)d_in[5];  // [512]
    float* out = (float*)d_out;                   // [16,2048,512]

    cudaFuncSetAttribute(mma_gemm, cudaFuncAttributeMaxDynamicSharedMemorySize,
                         SMEM_TOTAL);

    cudaStream_t st[NCHUNK];
    cudaEvent_t  evh[NCHUNK], evd[NCHUNK];
    for (int c = 0; c < NCHUNK; c++) {
        cudaStreamCreateWithFlags(&st[c], cudaStreamNonBlocking);
        cudaEventCreateWithFlags(&evh[c], cudaEventDisableTiming);
        cudaEventCreateWithFlags(&evd[c], cudaEventDisableTiming);
    }

    for (int c = 0; c < NCHUNK; c++) {
        // producer chunk on the capture (default) stream
        h_fused_kernel<<<HBLKS_PER_CHUNK, 256>>>(x, params, W1, b1, W2,
                                                 c * HBLKS_PER_CHUNK,
                                                 c == 0 ? 1 : 0);
        cudaEventRecord(evh[c], 0);
        // consumer chunk on its own stream, gated on its producer chunk
        cudaStreamWaitEvent(st[c], evh[c], 0);
        mma_gemm<<<dim3(EMB / BN, MTILES_PER_CHUNK), 128, SMEM_TOTAL, st[c]>>>(
            b2, out, c * MTILES_PER_CHUNK);
        cudaEventRecord(evd[c], st[c]);
    }
    // merge all side streams back into the capture stream
    for (int c = 0; c < NCHUNK; c++)
        cudaStreamWaitEvent(0, evd[c], 0);

    for (int c = 0; c < NCHUNK; c++) {
        cudaStreamDestroy(st[c]);      // deferred destruction; safe in capture
        cudaEventDestroy(evh[c]);
        cudaEventDestroy(evd[c]);
    }
}